// round 13
// baseline (speedup 1.0000x reference)
#include <cuda_runtime.h>
#include <cstdint>

// Problem constants (match reference generator)
#define BB    8            // batch
#define HH    32
#define WW    32
#define TT    4
#define BSs   3
#define DD    768
#define CELL_F   (BSs*DD)        // 2304 floats per cell
#define CELL_C   (CELL_F/8)      // 288 32-byte chunks per cell
#define THREADS  96              // 3 warps; 3 chunks (256-bit) per thread

// 256-bit global load/store (Blackwell LDG.E.256 / STG.E.256), streaming.
__device__ __forceinline__ void ldg256_cs(const float* p, float4& lo, float4& hi) {
    asm volatile("ld.global.cs.v8.f32 {%0,%1,%2,%3,%4,%5,%6,%7}, [%8];"
        : "=f"(lo.x), "=f"(lo.y), "=f"(lo.z), "=f"(lo.w),
          "=f"(hi.x), "=f"(hi.y), "=f"(hi.z), "=f"(hi.w)
        : "l"(p));
}
__device__ __forceinline__ void stg256_cs(float* p, const float4& lo, const float4& hi) {
    asm volatile("st.global.cs.v8.f32 [%0], {%1,%2,%3,%4,%5,%6,%7,%8};"
        :: "l"(p),
           "f"(lo.x), "f"(lo.y), "f"(lo.z), "f"(lo.w),
           "f"(hi.x), "f"(hi.y), "f"(hi.z), "f"(hi.w)
        : "memory");
}

// One patch per 96-thread block (finest balanced work quantum: coarse blocks
// do 4x the stores of fine ones, so small blocks minimize the end-of-kernel
// tail). Each thread front-batches 3 independent 256-bit loads covering the
// patch's 9216B payload, then stores to the 1 or 4 cells the patch covers.
// Effective rate is pinned at the HBM mixed read/write ceiling (~6.95 TB/s
// on 491 MB mandatory traffic) — invariant across all structural variants
// measured this session.
// The position tiling partitions the grid, so every output cell is written
// exactly once per launch (deterministic across graph replays).
__global__ __launch_bounds__(THREADS)
void apt_expand_kernel(const float* __restrict__ tok,
                       const int*   __restrict__ positions,
                       float*       __restrict__ out,
                       int P) {
    const int i = blockIdx.x;              // patch index over B*P
    const int tix = threadIdx.x;

    const int4 r = __ldg((const int4*)(positions + (size_t)i * 4));
    const int y = r.x, x = r.y, s = r.z, t = r.w;

    // Front-batch all 3 256-bit loads (coalesced, streaming: no reuse)
    const float* src = tok + (size_t)i * CELL_F;
    float4 lo0, hi0, lo1, hi1, lo2, hi2;
    ldg256_cs(src + (size_t)(tix              ) * 8, lo0, hi0);
    ldg256_cs(src + (size_t)(tix +     THREADS) * 8, lo1, hi1);
    ldg256_cs(src + (size_t)(tix + 2 * THREADS) * 8, lo2, hi2);

    const int b = i / P;
    const size_t cell0 = (((size_t)b * HH + y) * WW + x) * TT + t;
    float* d0 = out + cell0 * CELL_F + (size_t)tix * 8;

    if (s == 1) {
        // Fine patch (80%): single cell, straight-line 256-bit stores
        stg256_cs(d0,                   lo0, hi0);
        stg256_cs(d0 +     THREADS * 8, lo1, hi1);
        stg256_cs(d0 + 2 * THREADS * 8, lo2, hi2);
    } else {
        // Coarse 2x2 patch: 4 cells at constant offsets, all 12 stores ILP'd
        const size_t dX = (size_t)TT * CELL_F;        // +1 in x (floats)
        const size_t dY = (size_t)WW * TT * CELL_F;   // +1 in y
        float* d00 = d0;
        float* d01 = d0 + dX;
        float* d10 = d0 + dY;
        float* d11 = d0 + dY + dX;
        stg256_cs(d00, lo0, hi0);
        stg256_cs(d01, lo0, hi0);
        stg256_cs(d10, lo0, hi0);
        stg256_cs(d11, lo0, hi0);
        stg256_cs(d00 + THREADS * 8, lo1, hi1);
        stg256_cs(d01 + THREADS * 8, lo1, hi1);
        stg256_cs(d10 + THREADS * 8, lo1, hi1);
        stg256_cs(d11 + THREADS * 8, lo1, hi1);
        stg256_cs(d00 + 2 * THREADS * 8, lo2, hi2);
        stg256_cs(d01 + 2 * THREADS * 8, lo2, hi2);
        stg256_cs(d10 + 2 * THREADS * 8, lo2, hi2);
        stg256_cs(d11 + 2 * THREADS * 8, lo2, hi2);
    }
}

extern "C" void kernel_launch(void* const* d_in, const int* in_sizes, int n_in,
                              void* d_out, int out_size) {
    const float* tok = (const float*)d_in[0];       // modality_tokens [B, P*BS, D] fp32
    const int*   pos = (const int*)d_in[1];         // positions [B, P, 4] int32

    int P  = in_sizes[1] / (BB * 4);                // 2560
    int BP = BB * P;                                // 20480 patches

    apt_expand_kernel<<<BP, THREADS>>>(tok, pos, (float*)d_out, P);
}